// round 15
// baseline (speedup 1.0000x reference)
#include <cuda_runtime.h>
#include <math.h>

// Problem constants
#define S_N 16
#define B_N 128
#define T_N 200
#define L_N 64
#define R_N 16
#define H_N 256
#define NT  512
#define LP  68            // row stride for 64x64 mats: 16B-aligned rows
#define MTS 20            // transposed-m row stride
#define DIS 20            // diag-inverse block row stride
#define PS  20            // panel buffer row stride
#define W2S 68            // padded W2 row stride (bank-spread across h rows)
#define TRIN 2080

// ---- shared memory layout (float offsets) ----
#define O_W1  0
#define O_W2  (O_W1 + L_N*H_N)            // 16384
#define O_B1  (O_W2 + H_N*W2S)            // 16384 + 17408
#define O_B2  (O_B1 + H_N)
#define O_Z   (O_B2 + L_N)
#define O_SCR (O_Z + S_N*L_N)             // MLP hidden (4096) / G scratch (1920)
#define O_MT  (O_SCR + S_N*H_N)           // m transposed [l][s]
#define O_A   (O_MT + L_N*MTS)
#define O_BIT (O_A + L_N*LP)              // BIT[i][k] = invL[k][i]
#define O_DI  (O_BIT + L_N*LP)            // 4 diag-block inverses
#define O_KT  (O_DI + 4*16*DIS)
#define O_WT  (O_KT + L_N*R_N)
#define O_MP  (O_WT + S_N*L_N)
#define O_HF  (O_MP + L_N)
#define O_MF  (O_HF + L_N)
#define O_U   (O_MF + L_N)
#define O_KV  (O_U + L_N)
#define O_QD  (O_KV + L_N)
#define O_J0  (O_QD + L_N)
#define O_M0  (O_J0 + L_N)
#define O_SP  (O_M0 + L_N)
#define O_PAN (O_SP + L_N)                // panel buffer: 48 x PS
#define FLOAT_END (O_PAN + 48*PS)
// index tables (bytes)
#define BYTE_T64 (FLOAT_END*4)
#define BYTE_T48 (BYTE_T64 + TRIN*2)
#define BYTE_T32 (BYTE_T48 + 1176*2)
#define BYTE_T16 (BYTE_T32 + 528*2)
#define SMEM_BYTES (BYTE_T16 + 136*2)

// ---- output offsets ----
#define OFF_ZF 0LL
#define OFF_MFo ((long long)S_N*B_N*T_N*L_N)
#define OFF_MPo (OFF_MFo + (long long)B_N*T_N*L_N)
#define OFF_PF  (OFF_MPo + (long long)B_N*T_N*L_N)
#define OFF_PP  (OFF_PF + (long long)B_N*T_N*L_N*L_N)

__device__ __forceinline__ void trimap(int e, int &i, int &j) {
    int ii = (int)((sqrtf(8.0f*(float)e + 1.0f) - 1.0f) * 0.5f);
    while ((ii+1)*(ii+2)/2 <= e) ++ii;
    while (ii*(ii+1)/2 > e) --ii;
    i = ii;
    j = e - ii*(ii+1)/2;
}

__device__ __forceinline__ float dot4(float4 a, float4 b) {
    return a.x*b.x + a.y*b.y + a.z*b.z + a.w*b.w;
}

// ---- warp-level 16x16 Cholesky + inverse (one warp) ----
__device__ __forceinline__ void warp_diag(float* Ad, float* DIb, float* BITb, int lane) {
    const int r = lane & 15;
    float a[16];
    #pragma unroll
    for (int k = 0; k < 16; ++k) a[k] = Ad[r*LP + k];
    float mydiag = 1.0f;
    #pragma unroll
    for (int c = 0; c < 16; ++c) {
        float dc = __shfl_sync(0xffffffffu, a[c], c);
        float rd = rsqrtf(dc);
        if (r >= c) a[c] *= rd;
        if (r == c) mydiag = a[c];
        #pragma unroll
        for (int k = c + 1; k < 16; ++k) {
            float lkc = __shfl_sync(0xffffffffu, a[c], k);
            if (r >= k) a[k] -= a[c] * lkc;
        }
    }
    const float invd = 1.0f / mydiag;
    if (lane < 16) {
        #pragma unroll
        for (int k = 0; k < 16; ++k)
            if (k <= r) Ad[r*LP + k] = a[k];
    }
    float x[16];
    #pragma unroll
    for (int k = 0; k < 16; ++k) x[k] = 0.0f;
    #pragma unroll
    for (int rr = 0; rr < 16; ++rr) {
        float s = 0.0f;
        #pragma unroll
        for (int j = 0; j < 16; ++j) {
            if (j < rr) {
                float Lrj = __shfl_sync(0xffffffffu, a[j], rr);
                s += Lrj * x[j];
            }
        }
        float di = __shfl_sync(0xffffffffu, invd, rr);
        float v = ((r == rr ? 1.0f : 0.0f) - s) * di;
        x[rr] = (r <= rr) ? v : 0.0f;
    }
    if (lane < 16) {
        #pragma unroll
        for (int rr = 0; rr < 16; ++rr) DIb[rr*DIS + r] = x[rr];
        *(float4*)(BITb + r*LP + 0)  = make_float4(x[0],  x[1],  x[2],  x[3]);
        *(float4*)(BITb + r*LP + 4)  = make_float4(x[4],  x[5],  x[6],  x[7]);
        *(float4*)(BITb + r*LP + 8)  = make_float4(x[8],  x[9],  x[10], x[11]);
        *(float4*)(BITb + r*LP + 12) = make_float4(x[12], x[13], x[14], x[15]);
    }
}

// ---- pipelined blocked 64x64 Cholesky ----
__device__ __noinline__ void chol64_pipe(float* sA, float* sBIT, float* sDI,
                                         float* sPan, float* sG,
                                         const uchar2* T48, const uchar2* T32, const uchar2* T16,
                                         int tid) {
    const int lane = tid & 31;
    const int warp = tid >> 5;
    if (warp == 0) warp_diag(sA, sDI, sBIT, lane);
    __syncthreads();
    #pragma unroll 1
    for (int J = 0; J < 3; ++J) {
        const int base = 16*(J+1);
        const int nrow = 64 - base;
        // panel J -> sPan (rows base..63, cols of block J)
        #pragma unroll 1
        for (int e = tid; e < nrow*16; e += NT) {
            const int ir = e >> 4, c = e & 15;
            const float4* Ar = (const float4*)(sA + (base+ir)*LP + 16*J);
            const float4* Xr = (const float4*)(sDI + J*16*DIS + c*DIS);
            sPan[ir*PS + c] = dot4(Ar[0], Xr[0]) + dot4(Ar[1], Xr[1])
                            + dot4(Ar[2], Xr[2]) + dot4(Ar[3], Xr[3]);
        }
        __syncthreads();
        // update ONLY diag block (J+1,J+1): 136 entries, panel rows 0..15
        #pragma unroll 1
        for (int e = tid; e < 136; e += NT) {
            const uchar2 lj = T16[e];
            const float4* Li = (const float4*)(sPan + lj.x*PS);
            const float4* Lj = (const float4*)(sPan + lj.y*PS);
            sA[(base+lj.x)*LP + base + lj.y] -=
                dot4(Li[0], Lj[0]) + dot4(Li[1], Lj[1])
              + dot4(Li[2], Lj[2]) + dot4(Li[3], Lj[3]);
        }
        __syncthreads();
        // window: warp0 factors diag(J+1) ; warps 1-15 do the rest
        if (warp == 0) {
            warp_diag(sA + base*(LP+1), sDI + (J+1)*16*DIS, sBIT + base*(LP+1), lane);
        } else {
            const int et0 = tid - 32;
            if (J < 2) {
                const uchar2* TT = (J == 0) ? T48 : T32;
                const int rem = (J == 0) ? 1040 : 392;
                #pragma unroll 1
                for (int e = et0; e < rem; e += NT-32) {
                    const uchar2 lj = TT[136 + e];
                    const float4* Li = (const float4*)(sPan + lj.x*PS);
                    const float4* Lj = (const float4*)(sPan + lj.y*PS);
                    sA[(base+lj.x)*LP + base + lj.y] -=
                        dot4(Li[0], Lj[0]) + dot4(Li[1], Lj[1])
                      + dot4(Li[2], Lj[2]) + dot4(Li[3], Lj[3]);
                }
            } else {
                // G blocks (1,0),(2,0),(2,1) for triinv
                #pragma unroll 1
                for (int e = et0; e < 768; e += NT-32) {
                    const int blk = e >> 8, p = (e >> 4) & 15, q = e & 15;
                    const int I = (blk == 0) ? 1 : 2;
                    const int K = (blk == 2) ? 1 : 0;
                    const float4* xr = (const float4*)(sDI + I*16*DIS + p*DIS);
                    float gv[16];
                    *(float4*)(gv+0)  = xr[0]; *(float4*)(gv+4)  = xr[1];
                    *(float4*)(gv+8)  = xr[2]; *(float4*)(gv+12) = xr[3];
                    const float* Lc = sA + 16*I*LP + 16*K + q;
                    float s = 0.0f;
                    #pragma unroll
                    for (int r = 0; r < 16; ++r) s += gv[r] * Lc[r*LP];
                    sG[blk*(16*DIS) + p*DIS + q] = s;
                }
            }
            // copy panel J into sA (final L values)
            #pragma unroll 1
            for (int e = et0; e < nrow*4; e += NT-32) {
                const int ir = e >> 2, c4 = (e & 3) * 4;
                *(float4*)(sA + (base+ir)*LP + 16*J + c4) =
                    *(const float4*)(sPan + ir*PS + c4);
            }
        }
        __syncthreads();
    }
}

// ---- triangular inverse completion (G blocks for I=3, then phases) ----
__device__ __noinline__ void triinv64_rest(const float* sA, float* sBIT, float* sDI,
                                           float* G, int tid) {
    #pragma unroll 1
    for (int e = tid; e < 768; e += NT) {
        const int K = e >> 8, p = (e >> 4) & 15, q = e & 15;
        const int blk = 3 + K;
        const float4* xr = (const float4*)(sDI + 3*16*DIS + p*DIS);
        float gv[16];
        *(float4*)(gv+0)  = xr[0]; *(float4*)(gv+4)  = xr[1];
        *(float4*)(gv+8)  = xr[2]; *(float4*)(gv+12) = xr[3];
        const float* Lc = sA + 48*LP + 16*K + q;
        float s = 0.0f;
        #pragma unroll
        for (int r = 0; r < 16; ++r) s += gv[r] * Lc[r*LP];
        G[blk*(16*DIS) + p*DIS + q] = s;
    }
    __syncthreads();
    #pragma unroll 1
    for (int e = tid; e < 768; e += NT) {
        const int b = e >> 8, p = e & 15, q = (e >> 4) & 15;
        const int I = b + 1, Jb = b;
        const int gi = I*(I-1)/2 + (I-1);
        const float4* g4 = (const float4*)(G + gi*(16*DIS) + p*DIS);
        const float4* x4 = (const float4*)(sBIT + (16*Jb + q)*LP + 16*Jb);
        float s = dot4(g4[0], x4[0]) + dot4(g4[1], x4[1])
                + dot4(g4[2], x4[2]) + dot4(g4[3], x4[3]);
        sBIT[(16*Jb + q)*LP + 16*I + p] = -s;
    }
    __syncthreads();
    #pragma unroll 1
    for (int e = tid; e < 512; e += NT) {
        const int b = e >> 8, p = e & 15, q = (e >> 4) & 15;
        const int I = (b == 0) ? 2 : 3, Jb = (b == 0) ? 0 : 1;
        float s = 0.0f;
        #pragma unroll
        for (int K = 0; K < 2; ++K) {
            const int Kb = Jb + K;
            const float4* g4 = (const float4*)(G + (I*(I-1)/2 + Kb)*(16*DIS) + p*DIS);
            const float4* x4 = (const float4*)(sBIT + (16*Jb + q)*LP + 16*Kb);
            s += dot4(g4[0], x4[0]) + dot4(g4[1], x4[1])
               + dot4(g4[2], x4[2]) + dot4(g4[3], x4[3]);
        }
        sBIT[(16*Jb + q)*LP + 16*I + p] = -s;
    }
    __syncthreads();
    #pragma unroll 1
    for (int e = tid; e < 256; e += NT) {
        const int p = e & 15, q = (e >> 4) & 15;
        float s = 0.0f;
        #pragma unroll
        for (int Kb = 0; Kb < 3; ++Kb) {
            const float4* g4 = (const float4*)(G + (3 + Kb)*(16*DIS) + p*DIS);
            const float4* x4 = (const float4*)(sBIT + q*LP + 16*Kb);
            s += dot4(g4[0], x4[0]) + dot4(g4[1], x4[1])
               + dot4(g4[2], x4[2]) + dot4(g4[3], x4[3]);
        }
        sBIT[q*LP + 48 + p] = -s;
    }
    __syncthreads();
}

__global__ void __launch_bounds__(NT, 1)
nlf_kernel(const float* __restrict__ gk,  const float* __restrict__ gK,
           const float* __restrict__ glogQ, const float* __restrict__ gm0,
           const float* __restrict__ glogv0, const float* __restrict__ gW1,
           const float* __restrict__ gb1, const float* __restrict__ gW2,
           const float* __restrict__ gb2, const float* __restrict__ gw,
           float* __restrict__ out)
{
    extern __shared__ float sm[];
    const int tid = threadIdx.x;
    const int b   = blockIdx.x;

    uchar2* const T64 = (uchar2*)((char*)sm + BYTE_T64);
    uchar2* const T48 = (uchar2*)((char*)sm + BYTE_T48);
    uchar2* const T32 = (uchar2*)((char*)sm + BYTE_T32);
    uchar2* const T16 = (uchar2*)((char*)sm + BYTE_T16);

    // ---- one-time setup ----
    {
        const float4* g1 = (const float4*)gW1;
        float4* s1 = (float4*)(sm + O_W1);
        for (int i = tid; i < L_N*H_N/4; i += NT) s1[i] = g1[i];
        // W2 with padded row stride W2S (row = h, 16 float4 per row)
        const float4* g2 = (const float4*)gW2;
        for (int idx = tid; idx < H_N*L_N/4; idx += NT) {
            const int h = idx >> 4;
            const int l4 = (idx & 15) * 4;
            *(float4*)(sm + O_W2 + h*W2S + l4) = g2[idx];
        }
        if (tid < H_N) sm[O_B1 + tid] = gb1[tid];
        if (tid < L_N) {
            sm[O_B2 + tid] = gb2[tid];
            float q = glogQ[tid], v = glogv0[tid];
            float qd = fmaxf(q, 0.f) + log1pf(expf(-fabsf(q)));
            float p0 = fmaxf(v, 0.f) + log1pf(expf(-fabsf(v)));
            sm[O_QD + tid] = qd;
            sm[O_J0 + tid] = 1.0f / p0;
            sm[O_SP + tid] = sqrtf(p0);
            sm[O_M0 + tid] = gm0[tid];
        }
        for (int e = tid; e < TRIN; e += NT) { int i, j; trimap(e, i, j); T64[e] = make_uchar2((unsigned char)i, (unsigned char)j); }
        for (int e = tid; e < 1176; e += NT) { int i, j; trimap(e, i, j); T48[e] = make_uchar2((unsigned char)i, (unsigned char)j); }
        for (int e = tid; e < 528;  e += NT) { int i, j; trimap(e, i, j); T32[e] = make_uchar2((unsigned char)i, (unsigned char)j); }
        for (int e = tid; e < 136;  e += NT) { int i, j; trimap(e, i, j); T16[e] = make_uchar2((unsigned char)i, (unsigned char)j); }
    }
    __syncthreads();

    float* const sZ   = sm + O_Z;
    float* const sHID = sm + O_SCR;
    float* const sG   = sm + O_SCR;
    float* const sMT  = sm + O_MT;
    float* const sA   = sm + O_A;
    float* const sBIT = sm + O_BIT;
    float* const sDI  = sm + O_DI;
    float* const sKT  = sm + O_KT;
    float* const sWT  = sm + O_WT;
    float* const sMP  = sm + O_MP;
    float* const sHF  = sm + O_HF;
    float* const sMF  = sm + O_MF;
    float* const sU   = sm + O_U;
    float* const sKV  = sm + O_KV;
    float* const sPan = sm + O_PAN;

    #pragma unroll 1
    for (int t = 0; t < T_N; ++t) {
        // ---- stage K_t, w_t, k_t ----
        {
            const float4* gkt = (const float4*)(gK + ((long long)(b*T_N + t))*L_N*R_N);
            float4* s4 = (float4*)sKT;
            for (int i = tid; i < L_N*R_N/4; i += NT) s4[i] = gkt[i];
            if (tid < 256) {
                const int ss = tid >> 4;
                const int l4 = (tid & 15) * 4;
                const float4 wv = *(const float4*)(gw + (((long long)t*S_N + ss)*B_N + b)*L_N + l4);
                *(float4*)(sWT + ss*L_N + l4) = wv;
            }
            if (tid < L_N) sKV[tid] = gk[((long long)(b*T_N + t))*L_N + tid];
        }
        __syncthreads();

        if (t == 0) {
            if (tid < L_N) {
                sMP[tid] = sm[O_M0 + tid];
                sHF[tid] = sm[O_J0 + tid]*sm[O_M0 + tid] + sKV[tid];
            }
            // P_p_chol[0] = diag(sqrt(P0))
            {
                float4* po4 = (float4*)(out + OFF_PP + ((long long)(b*T_N + t))*L_N*L_N);
                for (int f = tid; f < 1024; f += NT) {
                    const int i = f >> 4, j0 = (f & 15) * 4;
                    float4 v;
                    v.x = (j0+0 == i) ? sm[O_SP + i] : 0.0f;
                    v.y = (j0+1 == i) ? sm[O_SP + i] : 0.0f;
                    v.z = (j0+2 == i) ? sm[O_SP + i] : 0.0f;
                    v.w = (j0+3 == i) ? sm[O_SP + i] : 0.0f;
                    po4[f] = v;
                }
            }
            // J_f = diag(J0) + K0 K0^T
            for (int e = tid; e < TRIN; e += NT) {
                const uchar2 ij = T64[e];
                const int i = ij.x, j = ij.y;
                const float4* ki = (const float4*)(sKT + i*R_N);
                const float4* kj = (const float4*)(sKT + j*R_N);
                float s = dot4(ki[0], kj[0]) + dot4(ki[1], kj[1])
                        + dot4(ki[2], kj[2]) + dot4(ki[3], kj[3]);
                if (i == j) s += sm[O_J0 + i];
                sA[i*LP + j] = s;
            }
            __syncthreads();
        } else {
            // ---- MLP layer 1: 2 samples x 4 h per thread, float4 weight loads ----
            {
                const int h4 = (tid & 63) * 4;
                const int s0 = (tid >> 6) * 2;
                const float4 bb = *(const float4*)(sm + O_B1 + h4);
                float a00=bb.x, a01=bb.y, a02=bb.z, a03=bb.w;
                float a10=bb.x, a11=bb.y, a12=bb.z, a13=bb.w;
                #pragma unroll 4
                for (int l = 0; l < L_N; l += 4) {
                    const float* wp = sm + O_W1 + l*H_N + h4;
                    const float4 w0 = *(const float4*)(wp);
                    const float4 w1 = *(const float4*)(wp + H_N);
                    const float4 w2 = *(const float4*)(wp + 2*H_N);
                    const float4 w3 = *(const float4*)(wp + 3*H_N);
                    const float4 za = *(const float4*)(sZ + (s0+0)*L_N + l);
                    const float4 zb = *(const float4*)(sZ + (s0+1)*L_N + l);
                    a00 += za.x*w0.x + za.y*w1.x + za.z*w2.x + za.w*w3.x;
                    a01 += za.x*w0.y + za.y*w1.y + za.z*w2.y + za.w*w3.y;
                    a02 += za.x*w0.z + za.y*w1.z + za.z*w2.z + za.w*w3.z;
                    a03 += za.x*w0.w + za.y*w1.w + za.z*w2.w + za.w*w3.w;
                    a10 += zb.x*w0.x + zb.y*w1.x + zb.z*w2.x + zb.w*w3.x;
                    a11 += zb.x*w0.y + zb.y*w1.y + zb.z*w2.y + zb.w*w3.y;
                    a12 += zb.x*w0.z + zb.y*w1.z + zb.z*w2.z + zb.w*w3.z;
                    a13 += zb.x*w0.w + zb.y*w1.w + zb.z*w2.w + zb.w*w3.w;
                }
                *(float4*)(sHID + (s0+0)*H_N + h4) =
                    make_float4(tanhf(a00), tanhf(a01), tanhf(a02), tanhf(a03));
                *(float4*)(sHID + (s0+1)*H_N + h4) =
                    make_float4(tanhf(a10), tanhf(a11), tanhf(a12), tanhf(a13));
            }
            __syncthreads();
            // ---- MLP layer 2: 4 l x 1 s per thread, h split in 2 (interleaved 4-chunks,
            //      stride 8, 32 iters covering all 256 h) + shfl-xor-1 combine.
            //      W2 rows padded to W2S=68 (conflict-free paired row loads). ----
            {
                const int hh  = tid & 1;
                const int lg  = (tid >> 1) & 15;
                const int s   = tid >> 5;           // warp-uniform
                const int lo4 = lg * 4;
                float a0 = 0.f, a1 = 0.f, a2 = 0.f, a3 = 0.f;
                const float* hidp  = sHID + s*H_N + hh*4;
                const float* wbase = sm + O_W2 + hh*4*W2S + lo4;
                #pragma unroll 4
                for (int k = 0; k < 32; ++k) {
                    const float4 hv = *(const float4*)(hidp + k*8);
                    const float* wp = wbase + k*8*W2S;
                    const float4 wa = *(const float4*)(wp);
                    const float4 wb = *(const float4*)(wp + W2S);
                    const float4 wc = *(const float4*)(wp + 2*W2S);
                    const float4 wd = *(const float4*)(wp + 3*W2S);
                    a0 += hv.x*wa.x + hv.y*wb.x + hv.z*wc.x + hv.w*wd.x;
                    a1 += hv.x*wa.y + hv.y*wb.y + hv.z*wc.y + hv.w*wd.y;
                    a2 += hv.x*wa.z + hv.y*wb.z + hv.z*wc.z + hv.w*wd.z;
                    a3 += hv.x*wa.w + hv.y*wb.w + hv.z*wc.w + hv.w*wd.w;
                }
                a0 += __shfl_xor_sync(0xffffffffu, a0, 1);
                a1 += __shfl_xor_sync(0xffffffffu, a1, 1);
                a2 += __shfl_xor_sync(0xffffffffu, a2, 1);
                a3 += __shfl_xor_sync(0xffffffffu, a3, 1);
                if (hh == 0) {
                    const float4 b4 = *(const float4*)(sm + O_B2 + lo4);
                    sMT[(lo4+0)*MTS + s] = a0 + b4.x;
                    sMT[(lo4+1)*MTS + s] = a1 + b4.y;
                    sMT[(lo4+2)*MTS + s] = a2 + b4.z;
                    sMT[(lo4+3)*MTS + s] = a3 + b4.w;
                }
            }
            __syncthreads();
            // ---- m_p ----
            if (tid < L_N) {
                const float4* mr = (const float4*)(sMT + tid*MTS);
                float4 m0v = mr[0], m1v = mr[1], m2v = mr[2], m3v = mr[3];
                sMP[tid] = (m0v.x+m0v.y+m0v.z+m0v.w + m1v.x+m1v.y+m1v.z+m1v.w
                          + m2v.x+m2v.y+m2v.z+m2v.w + m3v.x+m3v.y+m3v.z+m3v.w) * (1.0f/S_N);
            }
            __syncthreads();
            // ---- P_p build: 2x2 tiles via T32 (528 tasks) ----
            #pragma unroll 1
            for (int e = tid; e < 528; e += NT) {
                const uchar2 ac = T32[e];
                const int i0 = ac.x*2, j0 = ac.y*2;
                const float4* mi0 = (const float4*)(sMT + i0*MTS);
                const float4* mi1 = (const float4*)(sMT + (i0+1)*MTS);
                const float4* mj0 = (const float4*)(sMT + j0*MTS);
                const float4* mj1 = (const float4*)(sMT + (j0+1)*MTS);
                float s00 = 0.f, s01 = 0.f, s10 = 0.f, s11 = 0.f;
                #pragma unroll
                for (int r = 0; r < 4; ++r) {
                    const float4 vi0 = mi0[r], vi1 = mi1[r];
                    const float4 vj0 = mj0[r], vj1 = mj1[r];
                    s00 += dot4(vi0, vj0);
                    s01 += dot4(vi0, vj1);
                    s10 += dot4(vi1, vj0);
                    s11 += dot4(vi1, vj1);
                }
                const float mpi0 = sMP[i0], mpi1 = sMP[i0+1];
                const float mpj0 = sMP[j0], mpj1 = sMP[j0+1];
                float v00 = s00*(1.0f/S_N) - mpi0*mpj0;
                float v01 = s01*(1.0f/S_N) - mpi0*mpj1;
                float v10 = s10*(1.0f/S_N) - mpi1*mpj0;
                float v11 = s11*(1.0f/S_N) - mpi1*mpj1;
                if (i0 == j0) { v00 += sm[O_QD + i0]; v11 += sm[O_QD + i0+1]; }
                *(float2*)(sA + i0*LP + j0)     = make_float2(v00, v01);
                *(float2*)(sA + (i0+1)*LP + j0) = make_float2(v10, v11);
            }
            __syncthreads();

            chol64_pipe(sA, sBIT, sDI, sPan, sG, T48, T32, T16, tid);  // sA = Lp
            triinv64_rest(sA, sBIT, sDI, sG, tid);                     // sBIT = (Lp^{-1})^T

            // phase A: u = Lp^{-1} m_p (8 lanes/row) + write P_p_chol (Lp in sA)
            {
                const int i = tid >> 3, r = tid & 7;
                float s = 0.0f;
                for (int j = r; j <= i; j += 8) s += sBIT[j*LP + i] * sMP[j];
                s += __shfl_down_sync(0xffffffffu, s, 4, 8);
                s += __shfl_down_sync(0xffffffffu, s, 2, 8);
                s += __shfl_down_sync(0xffffffffu, s, 1, 8);
                if (r == 0) sU[i] = s;
            }
            {
                float4* po4 = (float4*)(out + OFF_PP + ((long long)(b*T_N + t))*L_N*L_N);
                for (int f = tid; f < 1024; f += NT) {
                    const int i = f >> 4, j0 = (f & 15) * 4;
                    float4 v;
                    v.x = (j0+0 <= i) ? sA[i*LP + j0+0] : 0.0f;
                    v.y = (j0+1 <= i) ? sA[i*LP + j0+1] : 0.0f;
                    v.z = (j0+2 <= i) ? sA[i*LP + j0+2] : 0.0f;
                    v.w = (j0+3 <= i) ? sA[i*LP + j0+3] : 0.0f;
                    po4[f] = v;
                }
            }
            __syncthreads();
            // phase B: h_f = Lp^{-T} u + k_t  and  J_f = BI^T BI + K K^T (2x2 tiles)
            {
                const int i = tid >> 3, r = tid & 7;
                float s = 0.0f;
                for (int k = i + r; k < L_N; k += 8) s += sBIT[i*LP + k] * sU[k];
                s += __shfl_down_sync(0xffffffffu, s, 4, 8);
                s += __shfl_down_sync(0xffffffffu, s, 2, 8);
                s += __shfl_down_sync(0xffffffffu, s, 1, 8);
                if (r == 0) sHF[i] = s + sKV[i];
            }
            #pragma unroll 1
            for (int e = tid; e < 528; e += NT) {
                const uchar2 ac = T32[e];
                const int i0 = ac.x*2, j0 = ac.y*2;
                float a00 = 0.f, a01 = 0.f, a10 = 0.f, a11 = 0.f;
                // K K^T part
                {
                    const float4* ki0 = (const float4*)(sKT + i0*R_N);
                    const float4* ki1 = (const float4*)(sKT + (i0+1)*R_N);
                    const float4* kj0 = (const float4*)(sKT + j0*R_N);
                    const float4* kj1 = (const float4*)(sKT + (j0+1)*R_N);
                    #pragma unroll
                    for (int r = 0; r < 4; ++r) {
                        const float4 vi0 = ki0[r], vi1 = ki1[r];
                        const float4 vj0 = kj0[r], vj1 = kj1[r];
                        a00 += dot4(vi0, vj0);
                        a01 += dot4(vi0, vj1);
                        a10 += dot4(vi1, vj0);
                        a11 += dot4(vi1, vj1);
                    }
                }
                // BI^T BI part (rows of BIT; k4 start valid for both rows since i0 even)
                {
                    const float4* bi0 = (const float4*)(sBIT + i0*LP);
                    const float4* bi1 = (const float4*)(sBIT + (i0+1)*LP);
                    const float4* bj0 = (const float4*)(sBIT + j0*LP);
                    const float4* bj1 = (const float4*)(sBIT + (j0+1)*LP);
                    #pragma unroll 2
                    for (int k4 = (i0 >> 2); k4 < 16; ++k4) {
                        const float4 vi0 = bi0[k4], vi1 = bi1[k4];
                        const float4 vj0 = bj0[k4], vj1 = bj1[k4];
                        a00 += dot4(vi0, vj0);
                        a01 += dot4(vi0, vj1);
                        a10 += dot4(vi1, vj0);
                        a11 += dot4(vi1, vj1);
                    }
                }
                *(float2*)(sA + i0*LP + j0)     = make_float2(a00, a01);
                *(float2*)(sA + (i0+1)*LP + j0) = make_float2(a10, a11);
            }
            __syncthreads();
        }

        // ================= common tail =================
        chol64_pipe(sA, sBIT, sDI, sPan, sG, T48, T32, T16, tid);  // sA = Lf
        triinv64_rest(sA, sBIT, sDI, sG, tid);                     // sBIT = (Lf^{-1})^T

        // u2 = Lf^{-1} h_f
        {
            const int i = tid >> 3, r = tid & 7;
            float s = 0.0f;
            for (int j = r; j <= i; j += 8) s += sBIT[j*LP + i] * sHF[j];
            s += __shfl_down_sync(0xffffffffu, s, 4, 8);
            s += __shfl_down_sync(0xffffffffu, s, 2, 8);
            s += __shfl_down_sync(0xffffffffu, s, 1, 8);
            if (r == 0) sU[i] = s;
        }
        __syncthreads();
        // m_f = Lf^{-T} u2 ; write m_p
        {
            const int i = tid >> 3, r = tid & 7;
            float s = 0.0f;
            for (int k = i + r; k < L_N; k += 8) s += sBIT[i*LP + k] * sU[k];
            s += __shfl_down_sync(0xffffffffu, s, 4, 8);
            s += __shfl_down_sync(0xffffffffu, s, 2, 8);
            s += __shfl_down_sync(0xffffffffu, s, 1, 8);
            if (r == 0) sMF[i] = s;
        }
        if (tid < L_N)
            out[OFF_MPo + ((long long)(b*T_N + t))*L_N + tid] = sMP[tid];
        __syncthreads();
        if (tid < L_N)
            out[OFF_MFo + ((long long)(b*T_N + t))*L_N + tid] = sMF[tid];
        // P_f_chol = (Lf^{-1})^T (upper)
        {
            float4* po4 = (float4*)(out + OFF_PF + ((long long)(b*T_N + t))*L_N*L_N);
            for (int f = tid; f < 1024; f += NT) {
                const int i = f >> 4, j0 = (f & 15) * 4;
                const float* bi = sBIT + i*LP;
                float4 v;
                v.x = (j0+0 >= i) ? bi[j0+0] : 0.0f;
                v.y = (j0+1 >= i) ? bi[j0+1] : 0.0f;
                v.z = (j0+2 >= i) ? bi[j0+2] : 0.0f;
                v.w = (j0+3 >= i) ? bi[j0+3] : 0.0f;
                po4[f] = v;
            }
        }
        // z_f[s] = m_f + Pf_chol @ w_t[s]
        {
            const int i  = tid & 63;
            const int s0 = (tid >> 6) * 2;
            const int k0 = i >> 2;
            float z0 = sMF[i], z1 = z0;
            const float4* bi4 = (const float4*)(sBIT + i*LP);
            const float4* w04 = (const float4*)(sWT + (s0+0)*L_N);
            const float4* w14 = (const float4*)(sWT + (s0+1)*L_N);
            #pragma unroll 2
            for (int j4 = k0; j4 < 16; ++j4) {
                const float4 bv = bi4[j4];
                z0 += dot4(bv, w04[j4]);
                z1 += dot4(bv, w14[j4]);
            }
            sZ[(s0+0)*L_N + i] = z0;
            sZ[(s0+1)*L_N + i] = z1;
            out[((((long long)(s0+0))*B_N + b)*T_N + t)*L_N + i] = z0;
            out[((((long long)(s0+1))*B_N + b)*T_N + t)*L_N + i] = z1;
        }
        __syncthreads();
    }
}

extern "C" void kernel_launch(void* const* d_in, const int* in_sizes, int n_in,
                              void* d_out, int out_size) {
    const float* gk     = (const float*)d_in[0];
    const float* gK     = (const float*)d_in[1];
    const float* glogQ  = (const float*)d_in[2];
    const float* gm0    = (const float*)d_in[3];
    const float* glogv0 = (const float*)d_in[4];
    const float* gW1    = (const float*)d_in[5];
    const float* gb1    = (const float*)d_in[6];
    const float* gW2    = (const float*)d_in[7];
    const float* gb2    = (const float*)d_in[8];
    const float* gw     = (const float*)d_in[9];
    float* out = (float*)d_out;

    const size_t smem = (size_t)SMEM_BYTES;
    cudaFuncSetAttribute(nlf_kernel, cudaFuncAttributeMaxDynamicSharedMemorySize, (int)smem);
    nlf_kernel<<<B_N, NT, smem>>>(gk, gK, glogQ, gm0, glogv0, gW1, gb1, gW2, gb2, gw, out);
}

// round 17
// speedup vs baseline: 1.0252x; 1.0252x over previous
#include <cuda_runtime.h>
#include <math.h>

// Problem constants
#define S_N 16
#define B_N 128
#define T_N 200
#define L_N 64
#define R_N 16
#define H_N 256
#define NT  512
#define LP  68            // row stride for 64x64 mats: 16B-aligned rows
#define MTS 20            // transposed-m row stride
#define DIS 20            // diag-inverse block row stride
#define PS  20            // panel buffer row stride
#define TRIN 2080

// ---- shared memory layout (float offsets) ----
#define O_W1  0
#define O_W2  (O_W1 + L_N*H_N)            // 16384
#define O_B1  (O_W2 + H_N*L_N)            // 32768
#define O_B2  (O_B1 + H_N)                // 33024
#define O_Z   (O_B2 + L_N)                // 33088
#define O_SCR (O_Z + S_N*L_N)             // 34112 : MLP hidden (4096) / G scratch (1920)
#define O_MT  (O_SCR + S_N*H_N)           // 38208 : m transposed [l][s]
#define O_A   (O_MT + L_N*MTS)            // 39488
#define O_BIT (O_A + L_N*LP)              // 43840 : BIT[i][k] = invL[k][i]
#define O_DI  (O_BIT + L_N*LP)            // 48192 : 4 diag-block inverses
#define O_KT  (O_DI + 4*16*DIS)           // 49472
#define O_WT  (O_KT + L_N*R_N)            // 50496
#define O_MP  (O_WT + S_N*L_N)            // 51520
#define O_HF  (O_MP + L_N)
#define O_MF  (O_HF + L_N)
#define O_U   (O_MF + L_N)
#define O_KV  (O_U + L_N)
#define O_QD  (O_KV + L_N)
#define O_J0  (O_QD + L_N)
#define O_M0  (O_J0 + L_N)
#define O_SP  (O_M0 + L_N)
#define O_PAN (O_SP + L_N)                // panel buffer: 48 x PS
#define FLOAT_END (O_PAN + 48*PS)
// index tables (bytes)
#define BYTE_T64 (FLOAT_END*4)
#define BYTE_T48 (BYTE_T64 + TRIN*2)
#define BYTE_T32 (BYTE_T48 + 1176*2)
#define BYTE_T16 (BYTE_T32 + 528*2)
#define SMEM_BYTES (BYTE_T16 + 136*2)

// ---- output offsets ----
#define OFF_ZF 0LL
#define OFF_MFo ((long long)S_N*B_N*T_N*L_N)
#define OFF_MPo (OFF_MFo + (long long)B_N*T_N*L_N)
#define OFF_PF  (OFF_MPo + (long long)B_N*T_N*L_N)
#define OFF_PP  (OFF_PF + (long long)B_N*T_N*L_N*L_N)

__device__ __forceinline__ void trimap(int e, int &i, int &j) {
    int ii = (int)((sqrtf(8.0f*(float)e + 1.0f) - 1.0f) * 0.5f);
    while ((ii+1)*(ii+2)/2 <= e) ++ii;
    while (ii*(ii+1)/2 > e) --ii;
    i = ii;
    j = e - ii*(ii+1)/2;
}

__device__ __forceinline__ float dot4(float4 a, float4 b) {
    return a.x*b.x + a.y*b.y + a.z*b.z + a.w*b.w;
}

// ---- warp-level 16x16 Cholesky + inverse (one warp) ----
__device__ __forceinline__ void warp_diag(float* Ad, float* DIb, float* BITb, int lane) {
    const int r = lane & 15;
    float a[16];
    #pragma unroll
    for (int k = 0; k < 16; ++k) a[k] = Ad[r*LP + k];
    float mydiag = 1.0f;
    #pragma unroll
    for (int c = 0; c < 16; ++c) {
        float dc = __shfl_sync(0xffffffffu, a[c], c);
        float rd = rsqrtf(dc);
        if (r >= c) a[c] *= rd;
        if (r == c) mydiag = a[c];
        #pragma unroll
        for (int k = c + 1; k < 16; ++k) {
            float lkc = __shfl_sync(0xffffffffu, a[c], k);
            if (r >= k) a[k] -= a[c] * lkc;
        }
    }
    const float invd = 1.0f / mydiag;
    if (lane < 16) {
        #pragma unroll
        for (int k = 0; k < 16; ++k)
            if (k <= r) Ad[r*LP + k] = a[k];
    }
    float x[16];
    #pragma unroll
    for (int k = 0; k < 16; ++k) x[k] = 0.0f;
    #pragma unroll
    for (int rr = 0; rr < 16; ++rr) {
        float s = 0.0f;
        #pragma unroll
        for (int j = 0; j < 16; ++j) {
            if (j < rr) {
                float Lrj = __shfl_sync(0xffffffffu, a[j], rr);
                s += Lrj * x[j];
            }
        }
        float di = __shfl_sync(0xffffffffu, invd, rr);
        float v = ((r == rr ? 1.0f : 0.0f) - s) * di;
        x[rr] = (r <= rr) ? v : 0.0f;
    }
    if (lane < 16) {
        #pragma unroll
        for (int rr = 0; rr < 16; ++rr) DIb[rr*DIS + r] = x[rr];
        *(float4*)(BITb + r*LP + 0)  = make_float4(x[0],  x[1],  x[2],  x[3]);
        *(float4*)(BITb + r*LP + 4)  = make_float4(x[4],  x[5],  x[6],  x[7]);
        *(float4*)(BITb + r*LP + 8)  = make_float4(x[8],  x[9],  x[10], x[11]);
        *(float4*)(BITb + r*LP + 12) = make_float4(x[12], x[13], x[14], x[15]);
    }
}

// ---- pipelined blocked 64x64 Cholesky ----
__device__ __noinline__ void chol64_pipe(float* sA, float* sBIT, float* sDI,
                                         float* sPan, float* sG,
                                         const uchar2* T48, const uchar2* T32, const uchar2* T16,
                                         int tid) {
    const int lane = tid & 31;
    const int warp = tid >> 5;
    if (warp == 0) warp_diag(sA, sDI, sBIT, lane);
    __syncthreads();
    #pragma unroll 1
    for (int J = 0; J < 3; ++J) {
        const int base = 16*(J+1);
        const int nrow = 64 - base;
        // panel J -> sPan (rows base..63, cols of block J)
        #pragma unroll 1
        for (int e = tid; e < nrow*16; e += NT) {
            const int ir = e >> 4, c = e & 15;
            const float4* Ar = (const float4*)(sA + (base+ir)*LP + 16*J);
            const float4* Xr = (const float4*)(sDI + J*16*DIS + c*DIS);
            sPan[ir*PS + c] = dot4(Ar[0], Xr[0]) + dot4(Ar[1], Xr[1])
                            + dot4(Ar[2], Xr[2]) + dot4(Ar[3], Xr[3]);
        }
        __syncthreads();
        // update ONLY diag block (J+1,J+1): 136 entries, panel rows 0..15
        #pragma unroll 1
        for (int e = tid; e < 136; e += NT) {
            const uchar2 lj = T16[e];
            const float4* Li = (const float4*)(sPan + lj.x*PS);
            const float4* Lj = (const float4*)(sPan + lj.y*PS);
            sA[(base+lj.x)*LP + base + lj.y] -=
                dot4(Li[0], Lj[0]) + dot4(Li[1], Lj[1])
              + dot4(Li[2], Lj[2]) + dot4(Li[3], Lj[3]);
        }
        __syncthreads();
        // window: warp0 factors diag(J+1) ; warps 1-15 do the rest
        if (warp == 0) {
            warp_diag(sA + base*(LP+1), sDI + (J+1)*16*DIS, sBIT + base*(LP+1), lane);
        } else {
            const int et0 = tid - 32;
            if (J < 2) {
                const uchar2* TT = (J == 0) ? T48 : T32;
                const int rem = (J == 0) ? 1040 : 392;
                #pragma unroll 1
                for (int e = et0; e < rem; e += NT-32) {
                    const uchar2 lj = TT[136 + e];
                    const float4* Li = (const float4*)(sPan + lj.x*PS);
                    const float4* Lj = (const float4*)(sPan + lj.y*PS);
                    sA[(base+lj.x)*LP + base + lj.y] -=
                        dot4(Li[0], Lj[0]) + dot4(Li[1], Lj[1])
                      + dot4(Li[2], Lj[2]) + dot4(Li[3], Lj[3]);
                }
            } else {
                // G blocks (1,0),(2,0),(2,1) for triinv
                #pragma unroll 1
                for (int e = et0; e < 768; e += NT-32) {
                    const int blk = e >> 8, p = (e >> 4) & 15, q = e & 15;
                    const int I = (blk == 0) ? 1 : 2;
                    const int K = (blk == 2) ? 1 : 0;
                    const float4* xr = (const float4*)(sDI + I*16*DIS + p*DIS);
                    float gv[16];
                    *(float4*)(gv+0)  = xr[0]; *(float4*)(gv+4)  = xr[1];
                    *(float4*)(gv+8)  = xr[2]; *(float4*)(gv+12) = xr[3];
                    const float* Lc = sA + 16*I*LP + 16*K + q;
                    float s = 0.0f;
                    #pragma unroll
                    for (int r = 0; r < 16; ++r) s += gv[r] * Lc[r*LP];
                    sG[blk*(16*DIS) + p*DIS + q] = s;
                }
            }
            // copy panel J into sA (final L values)
            #pragma unroll 1
            for (int e = et0; e < nrow*4; e += NT-32) {
                const int ir = e >> 2, c4 = (e & 3) * 4;
                *(float4*)(sA + (base+ir)*LP + 16*J + c4) =
                    *(const float4*)(sPan + ir*PS + c4);
            }
        }
        __syncthreads();
    }
}

// ---- triangular inverse completion (G blocks for I=3, then phases) ----
__device__ __noinline__ void triinv64_rest(const float* sA, float* sBIT, float* sDI,
                                           float* G, int tid) {
    #pragma unroll 1
    for (int e = tid; e < 768; e += NT) {
        const int K = e >> 8, p = (e >> 4) & 15, q = e & 15;
        const int blk = 3 + K;
        const float4* xr = (const float4*)(sDI + 3*16*DIS + p*DIS);
        float gv[16];
        *(float4*)(gv+0)  = xr[0]; *(float4*)(gv+4)  = xr[1];
        *(float4*)(gv+8)  = xr[2]; *(float4*)(gv+12) = xr[3];
        const float* Lc = sA + 48*LP + 16*K + q;
        float s = 0.0f;
        #pragma unroll
        for (int r = 0; r < 16; ++r) s += gv[r] * Lc[r*LP];
        G[blk*(16*DIS) + p*DIS + q] = s;
    }
    __syncthreads();
    #pragma unroll 1
    for (int e = tid; e < 768; e += NT) {
        const int b = e >> 8, p = e & 15, q = (e >> 4) & 15;
        const int I = b + 1, Jb = b;
        const int gi = I*(I-1)/2 + (I-1);
        const float4* g4 = (const float4*)(G + gi*(16*DIS) + p*DIS);
        const float4* x4 = (const float4*)(sBIT + (16*Jb + q)*LP + 16*Jb);
        float s = dot4(g4[0], x4[0]) + dot4(g4[1], x4[1])
                + dot4(g4[2], x4[2]) + dot4(g4[3], x4[3]);
        sBIT[(16*Jb + q)*LP + 16*I + p] = -s;
    }
    __syncthreads();
    #pragma unroll 1
    for (int e = tid; e < 512; e += NT) {
        const int b = e >> 8, p = e & 15, q = (e >> 4) & 15;
        const int I = (b == 0) ? 2 : 3, Jb = (b == 0) ? 0 : 1;
        float s = 0.0f;
        #pragma unroll
        for (int K = 0; K < 2; ++K) {
            const int Kb = Jb + K;
            const float4* g4 = (const float4*)(G + (I*(I-1)/2 + Kb)*(16*DIS) + p*DIS);
            const float4* x4 = (const float4*)(sBIT + (16*Jb + q)*LP + 16*Kb);
            s += dot4(g4[0], x4[0]) + dot4(g4[1], x4[1])
               + dot4(g4[2], x4[2]) + dot4(g4[3], x4[3]);
        }
        sBIT[(16*Jb + q)*LP + 16*I + p] = -s;
    }
    __syncthreads();
    #pragma unroll 1
    for (int e = tid; e < 256; e += NT) {
        const int p = e & 15, q = (e >> 4) & 15;
        float s = 0.0f;
        #pragma unroll
        for (int Kb = 0; Kb < 3; ++Kb) {
            const float4* g4 = (const float4*)(G + (3 + Kb)*(16*DIS) + p*DIS);
            const float4* x4 = (const float4*)(sBIT + q*LP + 16*Kb);
            s += dot4(g4[0], x4[0]) + dot4(g4[1], x4[1])
               + dot4(g4[2], x4[2]) + dot4(g4[3], x4[3]);
        }
        sBIT[q*LP + 48 + p] = -s;
    }
    __syncthreads();
}

__global__ void __launch_bounds__(NT, 1)
nlf_kernel(const float* __restrict__ gk,  const float* __restrict__ gK,
           const float* __restrict__ glogQ, const float* __restrict__ gm0,
           const float* __restrict__ glogv0, const float* __restrict__ gW1,
           const float* __restrict__ gb1, const float* __restrict__ gW2,
           const float* __restrict__ gb2, const float* __restrict__ gw,
           float* __restrict__ out)
{
    extern __shared__ float sm[];
    const int tid = threadIdx.x;
    const int b   = blockIdx.x;

    uchar2* const T64 = (uchar2*)((char*)sm + BYTE_T64);
    uchar2* const T48 = (uchar2*)((char*)sm + BYTE_T48);
    uchar2* const T32 = (uchar2*)((char*)sm + BYTE_T32);
    uchar2* const T16 = (uchar2*)((char*)sm + BYTE_T16);

    // ---- one-time setup ----
    {
        const float4* g1 = (const float4*)gW1;
        float4* s1 = (float4*)(sm + O_W1);
        for (int i = tid; i < L_N*H_N/4; i += NT) s1[i] = g1[i];
        const float4* g2 = (const float4*)gW2;
        float4* s2 = (float4*)(sm + O_W2);
        for (int i = tid; i < H_N*L_N/4; i += NT) s2[i] = g2[i];
        if (tid < H_N) sm[O_B1 + tid] = gb1[tid];
        if (tid < L_N) {
            sm[O_B2 + tid] = gb2[tid];
            float q = glogQ[tid], v = glogv0[tid];
            float qd = fmaxf(q, 0.f) + log1pf(expf(-fabsf(q)));
            float p0 = fmaxf(v, 0.f) + log1pf(expf(-fabsf(v)));
            sm[O_QD + tid] = qd;
            sm[O_J0 + tid] = 1.0f / p0;
            sm[O_SP + tid] = sqrtf(p0);
            sm[O_M0 + tid] = gm0[tid];
        }
        for (int e = tid; e < TRIN; e += NT) { int i, j; trimap(e, i, j); T64[e] = make_uchar2((unsigned char)i, (unsigned char)j); }
        for (int e = tid; e < 1176; e += NT) { int i, j; trimap(e, i, j); T48[e] = make_uchar2((unsigned char)i, (unsigned char)j); }
        for (int e = tid; e < 528;  e += NT) { int i, j; trimap(e, i, j); T32[e] = make_uchar2((unsigned char)i, (unsigned char)j); }
        for (int e = tid; e < 136;  e += NT) { int i, j; trimap(e, i, j); T16[e] = make_uchar2((unsigned char)i, (unsigned char)j); }
    }
    __syncthreads();

    float* const sZ   = sm + O_Z;
    float* const sHID = sm + O_SCR;
    float* const sG   = sm + O_SCR;
    float* const sMT  = sm + O_MT;
    float* const sA   = sm + O_A;
    float* const sBIT = sm + O_BIT;
    float* const sDI  = sm + O_DI;
    float* const sKT  = sm + O_KT;
    float* const sWT  = sm + O_WT;
    float* const sMP  = sm + O_MP;
    float* const sHF  = sm + O_HF;
    float* const sMF  = sm + O_MF;
    float* const sU   = sm + O_U;
    float* const sKV  = sm + O_KV;
    float* const sPan = sm + O_PAN;

    #pragma unroll 1
    for (int t = 0; t < T_N; ++t) {
        // ---- stage K_t, w_t, k_t (NO barrier for t>0: first consumer of
        //      sKT/sKV is phase B, sWT is z_f — both behind later barriers;
        //      previous step's loop-end barrier ordered the old readers). ----
        {
            const float4* gkt = (const float4*)(gK + ((long long)(b*T_N + t))*L_N*R_N);
            float4* s4 = (float4*)sKT;
            for (int i = tid; i < L_N*R_N/4; i += NT) s4[i] = gkt[i];
            if (tid < 256) {
                const int ss = tid >> 4;
                const int l4 = (tid & 15) * 4;
                const float4 wv = *(const float4*)(gw + (((long long)t*S_N + ss)*B_N + b)*L_N + l4);
                *(float4*)(sWT + ss*L_N + l4) = wv;
            }
            if (tid < L_N) sKV[tid] = gk[((long long)(b*T_N + t))*L_N + tid];
        }

        if (t == 0) {
            __syncthreads();    // t==0 consumes staged data immediately
            if (tid < L_N) {
                sMP[tid] = sm[O_M0 + tid];
                sHF[tid] = sm[O_J0 + tid]*sm[O_M0 + tid] + sKV[tid];
            }
            // P_p_chol[0] = diag(sqrt(P0))
            {
                float4* po4 = (float4*)(out + OFF_PP + ((long long)(b*T_N + t))*L_N*L_N);
                for (int f = tid; f < 1024; f += NT) {
                    const int i = f >> 4, j0 = (f & 15) * 4;
                    float4 v;
                    v.x = (j0+0 == i) ? sm[O_SP + i] : 0.0f;
                    v.y = (j0+1 == i) ? sm[O_SP + i] : 0.0f;
                    v.z = (j0+2 == i) ? sm[O_SP + i] : 0.0f;
                    v.w = (j0+3 == i) ? sm[O_SP + i] : 0.0f;
                    po4[f] = v;
                }
            }
            // J_f = diag(J0) + K0 K0^T
            for (int e = tid; e < TRIN; e += NT) {
                const uchar2 ij = T64[e];
                const int i = ij.x, j = ij.y;
                const float4* ki = (const float4*)(sKT + i*R_N);
                const float4* kj = (const float4*)(sKT + j*R_N);
                float s = dot4(ki[0], kj[0]) + dot4(ki[1], kj[1])
                        + dot4(ki[2], kj[2]) + dot4(ki[3], kj[3]);
                if (i == j) s += sm[O_J0 + i];
                sA[i*LP + j] = s;
            }
            __syncthreads();
        } else {
            // ---- MLP layer 1: 2 samples x 4 h per thread, float4 weight loads
            //      (overlaps the staging LDG/STS issued above) ----
            {
                const int h4 = (tid & 63) * 4;
                const int s0 = (tid >> 6) * 2;
                const float4 bb = *(const float4*)(sm + O_B1 + h4);
                float a00=bb.x, a01=bb.y, a02=bb.z, a03=bb.w;
                float a10=bb.x, a11=bb.y, a12=bb.z, a13=bb.w;
                #pragma unroll 4
                for (int l = 0; l < L_N; l += 4) {
                    const float* wp = sm + O_W1 + l*H_N + h4;
                    const float4 w0 = *(const float4*)(wp);
                    const float4 w1 = *(const float4*)(wp + H_N);
                    const float4 w2 = *(const float4*)(wp + 2*H_N);
                    const float4 w3 = *(const float4*)(wp + 3*H_N);
                    const float4 za = *(const float4*)(sZ + (s0+0)*L_N + l);
                    const float4 zb = *(const float4*)(sZ + (s0+1)*L_N + l);
                    a00 += za.x*w0.x + za.y*w1.x + za.z*w2.x + za.w*w3.x;
                    a01 += za.x*w0.y + za.y*w1.y + za.z*w2.y + za.w*w3.y;
                    a02 += za.x*w0.z + za.y*w1.z + za.z*w2.z + za.w*w3.z;
                    a03 += za.x*w0.w + za.y*w1.w + za.z*w2.w + za.w*w3.w;
                    a10 += zb.x*w0.x + zb.y*w1.x + zb.z*w2.x + zb.w*w3.x;
                    a11 += zb.x*w0.y + zb.y*w1.y + zb.z*w2.y + zb.w*w3.y;
                    a12 += zb.x*w0.z + zb.y*w1.z + zb.z*w2.z + zb.w*w3.z;
                    a13 += zb.x*w0.w + zb.y*w1.w + zb.z*w2.w + zb.w*w3.w;
                }
                *(float4*)(sHID + (s0+0)*H_N + h4) =
                    make_float4(tanhf(a00), tanhf(a01), tanhf(a02), tanhf(a03));
                *(float4*)(sHID + (s0+1)*H_N + h4) =
                    make_float4(tanhf(a10), tanhf(a11), tanhf(a12), tanhf(a13));
            }
            __syncthreads();
            // ---- MLP layer 2: 2 samples per thread -> sMT transposed [l][s]
            //      (scalar stride-1 weight loads: 1 smem wavefront each) ----
            {
                const int lo = tid & 63;
                const int s0 = (tid >> 6) * 2;
                const float bb2 = sm[O_B2 + lo];
                float a0 = bb2, a1 = bb2;
                #pragma unroll 4
                for (int h = 0; h < H_N; h += 4) {
                    const float w0 = sm[O_W2 + (h+0)*L_N + lo];
                    const float w1 = sm[O_W2 + (h+1)*L_N + lo];
                    const float w2 = sm[O_W2 + (h+2)*L_N + lo];
                    const float w3 = sm[O_W2 + (h+3)*L_N + lo];
                    float4 h0 = *(const float4*)(sHID + (s0+0)*H_N + h);
                    float4 h1 = *(const float4*)(sHID + (s0+1)*H_N + h);
                    a0 += h0.x*w0 + h0.y*w1 + h0.z*w2 + h0.w*w3;
                    a1 += h1.x*w0 + h1.y*w1 + h1.z*w2 + h1.w*w3;
                }
                *(float2*)(sMT + lo*MTS + s0) = make_float2(a0, a1);
            }
            __syncthreads();
            // ---- m_p ----
            if (tid < L_N) {
                const float4* mr = (const float4*)(sMT + tid*MTS);
                float4 m0v = mr[0], m1v = mr[1], m2v = mr[2], m3v = mr[3];
                sMP[tid] = (m0v.x+m0v.y+m0v.z+m0v.w + m1v.x+m1v.y+m1v.z+m1v.w
                          + m2v.x+m2v.y+m2v.z+m2v.w + m3v.x+m3v.y+m3v.z+m3v.w) * (1.0f/S_N);
            }
            __syncthreads();
            // ---- P_p build: 2x2 tiles via T32 (528 tasks) ----
            #pragma unroll 1
            for (int e = tid; e < 528; e += NT) {
                const uchar2 ac = T32[e];
                const int i0 = ac.x*2, j0 = ac.y*2;
                const float4* mi0 = (const float4*)(sMT + i0*MTS);
                const float4* mi1 = (const float4*)(sMT + (i0+1)*MTS);
                const float4* mj0 = (const float4*)(sMT + j0*MTS);
                const float4* mj1 = (const float4*)(sMT + (j0+1)*MTS);
                float s00 = 0.f, s01 = 0.f, s10 = 0.f, s11 = 0.f;
                #pragma unroll
                for (int r = 0; r < 4; ++r) {
                    const float4 vi0 = mi0[r], vi1 = mi1[r];
                    const float4 vj0 = mj0[r], vj1 = mj1[r];
                    s00 += dot4(vi0, vj0);
                    s01 += dot4(vi0, vj1);
                    s10 += dot4(vi1, vj0);
                    s11 += dot4(vi1, vj1);
                }
                const float mpi0 = sMP[i0], mpi1 = sMP[i0+1];
                const float mpj0 = sMP[j0], mpj1 = sMP[j0+1];
                float v00 = s00*(1.0f/S_N) - mpi0*mpj0;
                float v01 = s01*(1.0f/S_N) - mpi0*mpj1;
                float v10 = s10*(1.0f/S_N) - mpi1*mpj0;
                float v11 = s11*(1.0f/S_N) - mpi1*mpj1;
                if (i0 == j0) { v00 += sm[O_QD + i0]; v11 += sm[O_QD + i0+1]; }
                *(float2*)(sA + i0*LP + j0)     = make_float2(v00, v01);
                *(float2*)(sA + (i0+1)*LP + j0) = make_float2(v10, v11);
            }
            __syncthreads();

            chol64_pipe(sA, sBIT, sDI, sPan, sG, T48, T32, T16, tid);  // sA = Lp
            triinv64_rest(sA, sBIT, sDI, sG, tid);                     // sBIT = (Lp^{-1})^T

            // phase A: u = Lp^{-1} m_p (8 lanes/row) + write P_p_chol (Lp in sA)
            {
                const int i = tid >> 3, r = tid & 7;
                float s = 0.0f;
                for (int j = r; j <= i; j += 8) s += sBIT[j*LP + i] * sMP[j];
                s += __shfl_down_sync(0xffffffffu, s, 4, 8);
                s += __shfl_down_sync(0xffffffffu, s, 2, 8);
                s += __shfl_down_sync(0xffffffffu, s, 1, 8);
                if (r == 0) sU[i] = s;
            }
            {
                float4* po4 = (float4*)(out + OFF_PP + ((long long)(b*T_N + t))*L_N*L_N);
                for (int f = tid; f < 1024; f += NT) {
                    const int i = f >> 4, j0 = (f & 15) * 4;
                    float4 v;
                    v.x = (j0+0 <= i) ? sA[i*LP + j0+0] : 0.0f;
                    v.y = (j0+1 <= i) ? sA[i*LP + j0+1] : 0.0f;
                    v.z = (j0+2 <= i) ? sA[i*LP + j0+2] : 0.0f;
                    v.w = (j0+3 <= i) ? sA[i*LP + j0+3] : 0.0f;
                    po4[f] = v;
                }
            }
            __syncthreads();
            // phase B: h_f = Lp^{-T} u + k_t  and  J_f = BI^T BI + K K^T (2x2 tiles)
            {
                const int i = tid >> 3, r = tid & 7;
                float s = 0.0f;
                for (int k = i + r; k < L_N; k += 8) s += sBIT[i*LP + k] * sU[k];
                s += __shfl_down_sync(0xffffffffu, s, 4, 8);
                s += __shfl_down_sync(0xffffffffu, s, 2, 8);
                s += __shfl_down_sync(0xffffffffu, s, 1, 8);
                if (r == 0) sHF[i] = s + sKV[i];
            }
            #pragma unroll 1
            for (int e = tid; e < 528; e += NT) {
                const uchar2 ac = T32[e];
                const int i0 = ac.x*2, j0 = ac.y*2;
                float a00 = 0.f, a01 = 0.f, a10 = 0.f, a11 = 0.f;
                // K K^T part
                {
                    const float4* ki0 = (const float4*)(sKT + i0*R_N);
                    const float4* ki1 = (const float4*)(sKT + (i0+1)*R_N);
                    const float4* kj0 = (const float4*)(sKT + j0*R_N);
                    const float4* kj1 = (const float4*)(sKT + (j0+1)*R_N);
                    #pragma unroll
                    for (int r = 0; r < 4; ++r) {
                        const float4 vi0 = ki0[r], vi1 = ki1[r];
                        const float4 vj0 = kj0[r], vj1 = kj1[r];
                        a00 += dot4(vi0, vj0);
                        a01 += dot4(vi0, vj1);
                        a10 += dot4(vi1, vj0);
                        a11 += dot4(vi1, vj1);
                    }
                }
                // BI^T BI part (rows of BIT; k4 start valid for both rows since i0 even)
                {
                    const float4* bi0 = (const float4*)(sBIT + i0*LP);
                    const float4* bi1 = (const float4*)(sBIT + (i0+1)*LP);
                    const float4* bj0 = (const float4*)(sBIT + j0*LP);
                    const float4* bj1 = (const float4*)(sBIT + (j0+1)*LP);
                    #pragma unroll 2
                    for (int k4 = (i0 >> 2); k4 < 16; ++k4) {
                        const float4 vi0 = bi0[k4], vi1 = bi1[k4];
                        const float4 vj0 = bj0[k4], vj1 = bj1[k4];
                        a00 += dot4(vi0, vj0);
                        a01 += dot4(vi0, vj1);
                        a10 += dot4(vi1, vj0);
                        a11 += dot4(vi1, vj1);
                    }
                }
                *(float2*)(sA + i0*LP + j0)     = make_float2(a00, a01);
                *(float2*)(sA + (i0+1)*LP + j0) = make_float2(a10, a11);
            }
            __syncthreads();
        }

        // ================= common tail =================
        chol64_pipe(sA, sBIT, sDI, sPan, sG, T48, T32, T16, tid);  // sA = Lf
        triinv64_rest(sA, sBIT, sDI, sG, tid);                     // sBIT = (Lf^{-1})^T

        // u2 = Lf^{-1} h_f
        {
            const int i = tid >> 3, r = tid & 7;
            float s = 0.0f;
            for (int j = r; j <= i; j += 8) s += sBIT[j*LP + i] * sHF[j];
            s += __shfl_down_sync(0xffffffffu, s, 4, 8);
            s += __shfl_down_sync(0xffffffffu, s, 2, 8);
            s += __shfl_down_sync(0xffffffffu, s, 1, 8);
            if (r == 0) sU[i] = s;
        }
        __syncthreads();
        // m_f = Lf^{-T} u2 (fused global store) ; write m_p
        {
            const int i = tid >> 3, r = tid & 7;
            float s = 0.0f;
            for (int k = i + r; k < L_N; k += 8) s += sBIT[i*LP + k] * sU[k];
            s += __shfl_down_sync(0xffffffffu, s, 4, 8);
            s += __shfl_down_sync(0xffffffffu, s, 2, 8);
            s += __shfl_down_sync(0xffffffffu, s, 1, 8);
            if (r == 0) {
                sMF[i] = s;
                out[OFF_MFo + ((long long)(b*T_N + t))*L_N + i] = s;
            }
        }
        if (tid < L_N)
            out[OFF_MPo + ((long long)(b*T_N + t))*L_N + tid] = sMP[tid];
        __syncthreads();
        // P_f_chol = (Lf^{-1})^T (upper)
        {
            float4* po4 = (float4*)(out + OFF_PF + ((long long)(b*T_N + t))*L_N*L_N);
            for (int f = tid; f < 1024; f += NT) {
                const int i = f >> 4, j0 = (f & 15) * 4;
                const float* bi = sBIT + i*LP;
                float4 v;
                v.x = (j0+0 >= i) ? bi[j0+0] : 0.0f;
                v.y = (j0+1 >= i) ? bi[j0+1] : 0.0f;
                v.z = (j0+2 >= i) ? bi[j0+2] : 0.0f;
                v.w = (j0+3 >= i) ? bi[j0+3] : 0.0f;
                po4[f] = v;
            }
        }
        // z_f[s] = m_f + Pf_chol @ w_t[s]
        {
            const int i  = tid & 63;
            const int s0 = (tid >> 6) * 2;
            const int k0 = i >> 2;
            float z0 = sMF[i], z1 = z0;
            const float4* bi4 = (const float4*)(sBIT + i*LP);
            const float4* w04 = (const float4*)(sWT + (s0+0)*L_N);
            const float4* w14 = (const float4*)(sWT + (s0+1)*L_N);
            #pragma unroll 2
            for (int j4 = k0; j4 < 16; ++j4) {
                const float4 bv = bi4[j4];
                z0 += dot4(bv, w04[j4]);
                z1 += dot4(bv, w14[j4]);
            }
            sZ[(s0+0)*L_N + i] = z0;
            sZ[(s0+1)*L_N + i] = z1;
            out[((((long long)(s0+0))*B_N + b)*T_N + t)*L_N + i] = z0;
            out[((((long long)(s0+1))*B_N + b)*T_N + t)*L_N + i] = z1;
        }
        __syncthreads();
    }
}

extern "C" void kernel_launch(void* const* d_in, const int* in_sizes, int n_in,
                              void* d_out, int out_size) {
    const float* gk     = (const float*)d_in[0];
    const float* gK     = (const float*)d_in[1];
    const float* glogQ  = (const float*)d_in[2];
    const float* gm0    = (const float*)d_in[3];
    const float* glogv0 = (const float*)d_in[4];
    const float* gW1    = (const float*)d_in[5];
    const float* gb1    = (const float*)d_in[6];
    const float* gW2    = (const float*)d_in[7];
    const float* gb2    = (const float*)d_in[8];
    const float* gw     = (const float*)d_in[9];
    float* out = (float*)d_out;

    const size_t smem = (size_t)SMEM_BYTES;
    cudaFuncSetAttribute(nlf_kernel, cudaFuncAttributeMaxDynamicSharedMemorySize, (int)smem);
    nlf_kernel<<<B_N, NT, smem>>>(gk, gK, glogQ, gm0, glogv0, gW1, gb1, gW2, gb2, gw, out);
}